// round 1
// baseline (speedup 1.0000x reference)
#include <cuda_runtime.h>
#include <cstdint>

#define LGRID 512
#define BATCH 32768
#define TPB   256

__global__ __launch_bounds__(TPB)
void ode_euler_kernel(const float* __restrict__ s_grid,
                      const float* __restrict__ y0,
                      const float* __restrict__ w,
                      float* __restrict__ out) {
    __shared__ float sh_s[LGRID];
    __shared__ float sh_w[21];

    const int tid = threadIdx.x;
    for (int i = tid; i < LGRID; i += TPB) sh_s[i] = s_grid[i];
    if (tid < 21) sh_w[tid] = w[tid];
    __syncthreads();

    const float w0  = sh_w[0],  w1  = sh_w[1],  w2  = sh_w[2];
    const float w3  = sh_w[3],  w4  = sh_w[4],  w5  = sh_w[5];
    const float w6  = sh_w[6],  w7  = sh_w[7],  w8  = sh_w[8];
    const float w9  = sh_w[9],  w10 = sh_w[10], w11 = sh_w[11];
    const float w12 = sh_w[12], w13 = sh_w[13], w14 = sh_w[14];
    const float w15 = sh_w[15], w16 = sh_w[16], w17 = sh_w[17];
    const float w18 = sh_w[18], w19 = sh_w[19], w20 = sh_w[20];

    const int b = blockIdx.x * TPB + tid;

    float A = y0[0 * BATCH + b];
    float T = y0[1 * BATCH + b];
    float N = y0[2 * BATCH + b];
    float C = y0[3 * BATCH + b];

    // step 0: emit y0
    out[0 * BATCH + b] = A;
    out[1 * BATCH + b] = T;
    out[2 * BATCH + b] = N;
    out[3 * BATCH + b] = C;

    float s_prev = sh_s[0];

    #pragma unroll 4
    for (int i = 1; i < LGRID; ++i) {
        const float s_cur = sh_s[i];
        const float h = s_cur - s_prev;
        s_prev = s_cur;

        const float A2 = A * A;
        const float T2 = T * T;
        const float N2 = N * N;
        const float C2 = C * C;

        // dA = w0 + w1*A + w2*A^2
        float dA = fmaf(w2, A2, fmaf(w1, A, w0));
        // dT = w3 + w4*T + w5*T^2 + w6*A + w7*A^2 + w8*A*T
        float dT = fmaf(w4, T, w3);
        dT = fmaf(w5, T2, dT);
        dT = fmaf(w6, A, dT);
        dT = fmaf(w7, A2, dT);
        dT = fmaf(w8, A * T, dT);
        // dN = w9 + w10*N + w11*N^2 + w12*T + w13*T^2 + w14*T*N
        float dN = fmaf(w10, N, w9);
        dN = fmaf(w11, N2, dN);
        dN = fmaf(w12, T, dN);
        dN = fmaf(w13, T2, dN);
        dN = fmaf(w14, T * N, dN);
        // dC = w15 + w16*C + w17*C^2 + w18*N + w19*N^2 + w20*N*C
        float dC = fmaf(w16, C, w15);
        dC = fmaf(w17, C2, dC);
        dC = fmaf(w18, N, dC);
        dC = fmaf(w19, N2, dC);
        dC = fmaf(w20, N * C, dC);

        A = fmaf(h, dA, A);
        T = fmaf(h, dT, T);
        N = fmaf(h, dN, N);
        C = fmaf(h, dC, C);

        float* o = out + (size_t)i * (4 * BATCH) + b;
        o[0 * BATCH] = A;
        o[1 * BATCH] = T;
        o[2 * BATCH] = N;
        o[3 * BATCH] = C;
    }
}

extern "C" void kernel_launch(void* const* d_in, const int* in_sizes, int n_in,
                              void* d_out, int out_size) {
    const float* s_grid = (const float*)d_in[0];
    const float* y0     = (const float*)d_in[1];
    const float* w      = (const float*)d_in[2];
    float* out          = (float*)d_out;

    ode_euler_kernel<<<BATCH / TPB, TPB>>>(s_grid, y0, w, out);
}